// round 9
// baseline (speedup 1.0000x reference)
#include <cuda_runtime.h>
#include <cuda_bf16.h>
#include <cuda_fp16.h>
#include <mma.h>
#include <math.h>
#include <stdint.h>

using namespace nvcuda;

#define B_ROWS 8192
#define DIM    4096
#define NPH    128
#define K2     (2 * DIM)          // [h|l] split storage
#define LN_EPS 1e-5f
#define PI_F   3.14159265358979323846f

// ---------------- scratch (device globals) ----------------------------------
__device__ __nv_bfloat16 g_x2 [(size_t)B_ROWS * K2];    // x split [h|l]
__device__ __nv_bfloat16 g_wkq2[(size_t)NPH * K2];      // [Wk;Wq] split [h|l]
__device__ __half g_xh [(size_t)B_ROWS * DIM];          // x   fp16
__device__ __half g_wvh[(size_t)DIM * DIM];             // Wv  fp16
__device__ __half g_woh[(size_t)DIM * DIM];             // Wo  fp16
__device__ __half g_nh [(size_t)B_ROWS * DIM];          // normed fp16
__device__ float g_phase[3 * (size_t)B_ROWS * NPH];     // 3 split partials
__device__ float g_coef[B_ROWS];
__device__ float g_V[(size_t)B_ROWS * DIM];

// ---------------- PTX helpers ------------------------------------------------
__device__ __forceinline__ void cp_async16(void* smem, const void* gmem) {
    unsigned s = (unsigned)__cvta_generic_to_shared(smem);
    asm volatile("cp.async.cg.shared.global [%0], [%1], 16;\n" :: "r"(s), "l"(gmem));
}
__device__ __forceinline__ void cp_async16s(uint32_t s, const void* gmem) {
    asm volatile("cp.async.cg.shared.global [%0], [%1], 16;\n" :: "r"(s), "l"(gmem));
}
__device__ __forceinline__ void cp_commit() { asm volatile("cp.async.commit_group;\n"); }
template <int N> __device__ __forceinline__ void cp_wait() {
    asm volatile("cp.async.wait_group %0;\n" :: "n"(N));
}
__device__ __forceinline__ void ldmx4(uint32_t& r0, uint32_t& r1, uint32_t& r2, uint32_t& r3,
                                      uint32_t addr) {
    asm volatile("ldmatrix.sync.aligned.m8n8.x4.shared.b16 {%0,%1,%2,%3}, [%4];"
                 : "=r"(r0), "=r"(r1), "=r"(r2), "=r"(r3) : "r"(addr));
}
__device__ __forceinline__ void mma16816(float* c, uint32_t a0, uint32_t a1,
                                         uint32_t a2, uint32_t a3,
                                         uint32_t b0, uint32_t b1) {
    asm volatile("mma.sync.aligned.m16n8k16.row.col.f32.f16.f16.f32 "
                 "{%0,%1,%2,%3}, {%4,%5,%6,%7}, {%8,%9}, {%0,%1,%2,%3};"
                 : "+f"(c[0]), "+f"(c[1]), "+f"(c[2]), "+f"(c[3])
                 : "r"(a0), "r"(a1), "r"(a2), "r"(a3), "r"(b0), "r"(b1));
}
__device__ __forceinline__ uint32_t smem_u32(const void* p) {
    uint32_t a;
    asm("{ .reg .u64 t; cvta.to.shared.u64 t, %1; cvt.u32.u64 %0, t; }" : "=r"(a) : "l"(p));
    return a;
}

// --------- x prep: one read -> bf16 [h|l] split AND fp16 ---------------------
__global__ void prep_x(const float* __restrict__ in, size_t n_vec4) {
    size_t i = (size_t)blockIdx.x * blockDim.x + threadIdx.x;
    if (i >= n_vec4) return;
    size_t e = i * 4;
    size_t r = e / DIM;
    int    k = (int)(e % DIM);
    float4 v = *reinterpret_cast<const float4*>(in + e);
    float vv[4] = {v.x, v.y, v.z, v.w};
    union { __nv_bfloat16 b[4]; uint2 u; } H, L;
#pragma unroll
    for (int q = 0; q < 4; q++) {
        H.b[q] = __float2bfloat16_rn(vv[q]);
        L.b[q] = __float2bfloat16_rn(vv[q] - __bfloat162float(H.b[q]));
    }
    __nv_bfloat16* o = g_x2 + r * (size_t)K2 + k;
    *reinterpret_cast<uint2*>(o)       = H.u;
    *reinterpret_cast<uint2*>(o + DIM) = L.u;
    __half2 h0 = __floats2half2_rn(v.x, v.y);
    __half2 h1 = __floats2half2_rn(v.z, v.w);
    uint2 u = {*reinterpret_cast<uint32_t*>(&h0), *reinterpret_cast<uint32_t*>(&h1)};
    *reinterpret_cast<uint2*>(g_xh + e) = u;
}

// ---------------- weight split [h|l] (phase path) ----------------------------
__global__ void split2_w(const float* __restrict__ in, __nv_bfloat16* __restrict__ out,
                         size_t n_vec4) {
    size_t i = (size_t)blockIdx.x * blockDim.x + threadIdx.x;
    if (i >= n_vec4) return;
    size_t e = i * 4;
    size_t r = e / DIM;
    int    k = (int)(e % DIM);
    float4 v = *reinterpret_cast<const float4*>(in + e);
    float vv[4] = {v.x, v.y, v.z, v.w};
    union { __nv_bfloat16 b[4]; uint2 u; } H, L;
#pragma unroll
    for (int q = 0; q < 4; q++) {
        H.b[q] = __float2bfloat16_rn(vv[q]);
        L.b[q] = __float2bfloat16_rn(vv[q] - __bfloat162float(H.b[q]));
    }
    __nv_bfloat16* o = out + r * (size_t)K2 + k;
    *reinterpret_cast<uint2*>(o)       = H.u;
    *reinterpret_cast<uint2*>(o + DIM) = L.u;
}

// ---------------- fp32 -> fp16 convert ---------------------------------------
__global__ void to_half(const float* __restrict__ in, __half* __restrict__ out, size_t n_vec4) {
    size_t i = (size_t)blockIdx.x * blockDim.x + threadIdx.x;
    if (i >= n_vec4) return;
    float4 v = *reinterpret_cast<const float4*>(in + i * 4);
    __half2 h0 = __floats2half2_rn(v.x, v.y);
    __half2 h1 = __floats2half2_rn(v.z, v.w);
    uint2 u = {*reinterpret_cast<uint32_t*>(&h0), *reinterpret_cast<uint32_t*>(&h1)};
    *reinterpret_cast<uint2*>(out + i * 4) = u;
}

// ---------------- per-row phase alignment -> coef (sums 3 partials) ----------
__global__ void coef_kernel(const float* __restrict__ bk, const float* __restrict__ bq) {
    int row  = blockIdx.x * 8 + (threadIdx.x >> 5);
    int lane = threadIdx.x & 31;
    const size_t SEG = (size_t)B_ROWS * NPH;
    const float* ph = &g_phase[(size_t)row * NPH];
    float s = 0.f;
#pragma unroll
    for (int p = lane; p < 64; p += 32) {
        float rk = ph[p]      + ph[SEG + p]      + ph[2*SEG + p];
        float rq = ph[64 + p] + ph[SEG + 64 + p] + ph[2*SEG + 64 + p];
        float kp = tanhf(rk + bk[p]) * PI_F;
        float qp = tanhf(rq + bq[p]) * PI_F;
        s += cosf(kp - qp);
    }
#pragma unroll
    for (int o = 16; o; o >>= 1) s += __shfl_xor_sync(0xffffffffu, s, o);
    if (lane == 0) {
        float gain = log1pf(expf(s * (1.0f / 64.0f) + 0.5f));
        g_coef[row] = s * gain * (1.0f / 64.0f);
    }
}

// ------- fused bias + row-scale + LayerNorm -> fp16 normed -------------------
__global__ __launch_bounds__(256) void ln_kernel(const float* __restrict__ bv,
                                                 const float* __restrict__ ln_g,
                                                 const float* __restrict__ ln_b) {
    int row = blockIdx.x;
    const float* vr = g_V + (size_t)row * DIM;
    __half* nr = g_nh + (size_t)row * DIM;
    float coef = g_coef[row];
    int tid = threadIdx.x;

    float vals[16];
    float sum = 0.f, sq = 0.f;
#pragma unroll
    for (int j = 0; j < 4; j++) {
        int k = (tid + j * 256) * 4;
        float4 v = *reinterpret_cast<const float4*>(vr + k);
        float4 b = *reinterpret_cast<const float4*>(bv + k);
        float t0 = (v.x + b.x) * coef, t1 = (v.y + b.y) * coef;
        float t2 = (v.z + b.z) * coef, t3 = (v.w + b.w) * coef;
        vals[j*4+0]=t0; vals[j*4+1]=t1; vals[j*4+2]=t2; vals[j*4+3]=t3;
        sum += t0+t1+t2+t3;
        sq  += t0*t0+t1*t1+t2*t2+t3*t3;
    }
    __shared__ float s1[8], s2[8];
#pragma unroll
    for (int o = 16; o; o >>= 1) {
        sum += __shfl_xor_sync(0xffffffffu, sum, o);
        sq  += __shfl_xor_sync(0xffffffffu, sq,  o);
    }
    int warp = tid >> 5, lane = tid & 31;
    if (lane == 0) { s1[warp] = sum; s2[warp] = sq; }
    __syncthreads();
    sum = 0.f; sq = 0.f;
#pragma unroll
    for (int w = 0; w < 8; w++) { sum += s1[w]; sq += s2[w]; }

    float mu   = sum * (1.0f / DIM);
    float var  = sq * (1.0f / DIM) - mu * mu;
    float rstd = rsqrtf(var + LN_EPS);
#pragma unroll
    for (int j = 0; j < 4; j++) {
        int k = (tid + j * 256) * 4;
        float4 g = *reinterpret_cast<const float4*>(ln_g + k);
        float4 bb = *reinterpret_cast<const float4*>(ln_b + k);
        __half2 h0 = __floats2half2_rn((vals[j*4+0]-mu)*rstd*g.x + bb.x,
                                       (vals[j*4+1]-mu)*rstd*g.y + bb.y);
        __half2 h1 = __floats2half2_rn((vals[j*4+2]-mu)*rstd*g.z + bb.z,
                                       (vals[j*4+3]-mu)*rstd*g.w + bb.w);
        uint2 u = {*reinterpret_cast<uint32_t*>(&h0), *reinterpret_cast<uint32_t*>(&h1)};
        *reinterpret_cast<uint2*>(nr + k) = u;
    }
}

// =========== phase GEMM (bf16x3 via 3 segment-pair passes, wmma) ==============
constexpr int BM = 128, BN = 128, BKE = 64;
constexpr int LDSB = 72;
constexpr int STAGES = 3;
constexpr int STAGE_ELEMS = BM * LDSB;
constexpr size_t PH_SMEM = (size_t)STAGES * 2 * STAGE_ELEMS * 2;

__global__ __launch_bounds__(256, 2) void gemm_phase(
    const __nv_bfloat16* __restrict__ A, const __nv_bfloat16* __restrict__ Bw,
    float* __restrict__ C, int M, int N, int K)
{
    typedef __nv_bfloat16 T;
    extern __shared__ __align__(128) unsigned char dsmem[];
    T* sA = reinterpret_cast<T*>(dsmem);
    T* sB = sA + STAGES * STAGE_ELEMS;

    int seg = blockIdx.y;
    A  += (seg == 2) ? DIM : 0;
    Bw += (seg == 1) ? DIM : 0;
    C  += (size_t)seg * (size_t)M * N;

    int tid  = threadIdx.x;
    int warp = tid >> 5;
    int lane = tid & 31;

    int m0 = blockIdx.x * BM;
    int wm = (warp & 3) * 32;
    int wn = (warp >> 2) * 64;

    int chunk = tid & 7;
    int row0  = tid >> 3;

    const T* gA = A + (size_t)m0 * K2 + chunk * 8;
    const T* gB = Bw + chunk * 8;

    auto load_tile = [&](int kt, int stg) {
        size_t koff = (size_t)kt * BKE;
        T* dA = sA + stg * STAGE_ELEMS + chunk * 8;
        T* dB = sB + stg * STAGE_ELEMS + chunk * 8;
#pragma unroll
        for (int p = 0; p < 4; p++) {
            int r = row0 + p * 32;
            cp_async16(dA + r * LDSB, gA + (size_t)r * K2 + koff);
            cp_async16(dB + r * LDSB, gB + (size_t)r * K2 + koff);
        }
    };

    wmma::fragment<wmma::accumulator, 16, 16, 16, float> acc[2][4];
#pragma unroll
    for (int i = 0; i < 2; i++)
#pragma unroll
        for (int j = 0; j < 4; j++) wmma::fill_fragment(acc[i][j], 0.0f);

    const int nt = K / BKE;
#pragma unroll
    for (int s = 0; s < STAGES - 1; s++) { load_tile(s, s); cp_commit(); }

    for (int it = 0; it < nt; it++) {
        cp_wait<STAGES - 2>();
        __syncthreads();
        int pre = it + STAGES - 1;
        if (pre < nt) { load_tile(pre, pre % STAGES); cp_commit(); }

        const T* tA = sA + (it % STAGES) * STAGE_ELEMS;
        const T* tB = sB + (it % STAGES) * STAGE_ELEMS;
#pragma unroll
        for (int ks = 0; ks < BKE; ks += 16) {
            wmma::fragment<wmma::matrix_a, 16, 16, 16, T, wmma::row_major> af[2];
            wmma::fragment<wmma::matrix_b, 16, 16, 16, T, wmma::col_major> bf[4];
#pragma unroll
            for (int i = 0; i < 2; i++)
                wmma::load_matrix_sync(af[i], tA + (wm + i * 16) * LDSB + ks, LDSB);
#pragma unroll
            for (int j = 0; j < 4; j++)
                wmma::load_matrix_sync(bf[j], tB + (wn + j * 16) * LDSB + ks, LDSB);
#pragma unroll
            for (int i = 0; i < 2; i++)
#pragma unroll
                for (int j = 0; j < 4; j++)
                    wmma::mma_sync(acc[i][j], af[i], bf[j], acc[i][j]);
        }
    }

    cp_wait<0>();
    __syncthreads();

    float* stage = reinterpret_cast<float*>(dsmem) + warp * 320;
#pragma unroll
    for (int i = 0; i < 2; i++) {
#pragma unroll
        for (int j = 0; j < 4; j++) {
            wmma::store_matrix_sync(stage, acc[i][j], 20, wmma::mem_row_major);
            __syncwarp();
            int gm = m0 + wm + i * 16;
            int gn = wn + j * 16;
#pragma unroll
            for (int e = 0; e < 8; e++) {
                int idx = e * 32 + lane;
                int rr = idx >> 4;
                int cc = idx & 15;
                C[(size_t)(gm + rr) * N + gn + cc] = stage[rr * 20 + cc];
            }
            __syncwarp();
        }
    }
}

// ======== big GEMM v2: 128x256 tile, warp tile 64x64, raw mma.sync ===========
// 8 warps (2 M-groups x 4 N-groups), BK=64 halves, 4 stages, 1 CTA/SM.
// MODE 0: C = acc     MODE 1: C = acc + bias[n] + addend[m*N+n]
constexpr int BM2 = 128, BN2 = 256, BK2 = 64;
constexpr int STG2 = 4;
constexpr int A_BYTES = BM2 * 128;                 // 16 KB
constexpr int B_BYTES = BN2 * 128;                 // 32 KB
constexpr int STAGE_BYTES = A_BYTES + B_BYTES;     // 48 KB
constexpr size_t BIG_SMEM = (size_t)STG2 * STAGE_BYTES;  // 196608

template <int MODE>
__global__ __launch_bounds__(256, 1) void gemm_big(
    const __half* __restrict__ A, const __half* __restrict__ Bw,
    float* __restrict__ C, int M, int N, int K,
    const float* __restrict__ bias, const float* __restrict__ addend)
{
    extern __shared__ __align__(128) unsigned char dsmem[];
    uint32_t sb = smem_u32(dsmem);
    uint32_t sA = sb;                        // stage s at sA + s*STAGE_BYTES
    uint32_t sB = sb + A_BYTES;              // stage s at sB + s*STAGE_BYTES

    int tid  = threadIdx.x;
    int warp = tid >> 5;
    int lane = tid & 31;

    const int num_m = M / BM2, num_n = N / BN2;
    const int GROUP = 8;
    int id = blockIdx.x;
    int group_size = GROUP * num_n;
    int gid = id / group_size;
    int first_m = gid * GROUP;
    int gm_sz = (num_m - first_m) < GROUP ? (num_m - first_m) : GROUP;
    int pid_m = first_m + (id % group_size) % gm_sz;
    int pid_n = (id % group_size) / gm_sz;
    int m0 = pid_m * BM2;
    int n0 = pid_n * BN2;

    int wm = (warp & 1) * 64;    // 2 warp-rows
    int wn = (warp >> 1) * 64;   // 4 warp-cols

    // gmem load geometry (16B chunks, 8 per 128B row)
    int chunk = tid & 7;
    int row0  = tid >> 3;        // 0..31
    const __half* gA = A  + (size_t)m0 * K + chunk * 8;
    const __half* gB = Bw + (size_t)n0 * K + chunk * 8;

    auto load_tile = [&](int kt, int stg) {
        size_t koff = (size_t)kt * BK2;
        uint32_t dA = sA + stg * STAGE_BYTES;
        uint32_t dB = sB + stg * STAGE_BYTES;
        uint32_t cs = (uint32_t)(chunk * 16);
#pragma unroll
        for (int p = 0; p < 4; p++) {        // A: 128 rows
            int r = row0 + p * 32;
            uint32_t so = r * 128 + (cs ^ ((r & 7) << 4));
            cp_async16s(dA + so, gA + (size_t)r * K + koff);
        }
#pragma unroll
        for (int p = 0; p < 8; p++) {        // B: 256 rows
            int r = row0 + p * 32;
            uint32_t so = r * 128 + (cs ^ ((r & 7) << 4));
            cp_async16s(dB + so, gB + (size_t)r * K + koff);
        }
    };

    // ldmatrix per-lane geometry
    int lr = lane & 15;
    int kb = lane >> 4;
    uint32_t xv = (uint32_t)((lr & 7) << 4);
    uint32_t aRow0 = (uint32_t)(wm + lr) * 128;
    uint32_t bRow0 = (uint32_t)(wn + lr) * 128;

    float acc[4][8][4];
#pragma unroll
    for (int i = 0; i < 4; i++)
#pragma unroll
        for (int j = 0; j < 8; j++)
#pragma unroll
            for (int q = 0; q < 4; q++) acc[i][j][q] = 0.f;

    const int nt = K / BK2;
#pragma unroll
    for (int s = 0; s < STG2 - 1; s++) { load_tile(s, s); cp_commit(); }

    for (int it = 0; it < nt; it++) {
        cp_wait<STG2 - 2>();
        __syncthreads();
        int pre = it + STG2 - 1;
        if (pre < nt) { load_tile(pre, pre % STG2); cp_commit(); }

        uint32_t tA = sA + (it % STG2) * STAGE_BYTES;
        uint32_t tB = sB + (it % STG2) * STAGE_BYTES;
#pragma unroll
        for (int s16 = 0; s16 < 4; s16++) {          // 4 x k16 steps
            uint32_t col = (uint32_t)((s16 * 32 + kb * 16)) ^ xv;
            uint32_t a[4][4];
#pragma unroll
            for (int mi = 0; mi < 4; mi++)
                ldmx4(a[mi][0], a[mi][1], a[mi][2], a[mi][3],
                      tA + aRow0 + (uint32_t)(mi * 16 * 128) + col);
            uint32_t b[4][4];
#pragma unroll
            for (int nb = 0; nb < 4; nb++)
                ldmx4(b[nb][0], b[nb][1], b[nb][2], b[nb][3],
                      tB + bRow0 + (uint32_t)(nb * 16 * 128) + col);
#pragma unroll
            for (int mi = 0; mi < 4; mi++)
#pragma unroll
                for (int nb = 0; nb < 4; nb++) {
                    mma16816(acc[mi][nb * 2 + 0], a[mi][0], a[mi][1], a[mi][2], a[mi][3],
                             b[nb][0], b[nb][2]);
                    mma16816(acc[mi][nb * 2 + 1], a[mi][0], a[mi][1], a[mi][2], a[mi][3],
                             b[nb][1], b[nb][3]);
                }
        }
    }

    cp_wait<0>();

    // direct register epilogue
    int mrow = m0 + wm + (lane >> 2);
    int ncol = n0 + wn + (lane & 3) * 2;
#pragma unroll
    for (int mi = 0; mi < 4; mi++) {
#pragma unroll
        for (int nj = 0; nj < 8; nj++) {
            int n = ncol + nj * 8;
            size_t go0 = (size_t)(mrow + mi * 16)     * N + n;
            size_t go1 = (size_t)(mrow + mi * 16 + 8) * N + n;
            float2 v0 = {acc[mi][nj][0], acc[mi][nj][1]};
            float2 v1 = {acc[mi][nj][2], acc[mi][nj][3]};
            if (MODE == 1) {
                float2 bb = *reinterpret_cast<const float2*>(bias + n);
                float2 a0 = *reinterpret_cast<const float2*>(addend + go0);
                float2 a1 = *reinterpret_cast<const float2*>(addend + go1);
                v0.x += bb.x + a0.x; v0.y += bb.y + a0.y;
                v1.x += bb.x + a1.x; v1.y += bb.y + a1.y;
            }
            *reinterpret_cast<float2*>(C + go0) = v0;
            *reinterpret_cast<float2*>(C + go1) = v1;
        }
    }
}

// ---------------- launch -----------------------------------------------------
extern "C" void kernel_launch(void* const* d_in, const int* in_sizes, int n_in,
                              void* d_out, int out_size) {
    const float* x    = (const float*)d_in[0];
    const float* Wk   = (const float*)d_in[1];
    const float* bk   = (const float*)d_in[2];
    const float* Wq   = (const float*)d_in[3];
    const float* bq   = (const float*)d_in[4];
    const float* Wv   = (const float*)d_in[5];
    const float* bv   = (const float*)d_in[6];
    const float* ln_g = (const float*)d_in[7];
    const float* ln_b = (const float*)d_in[8];
    const float* Wo   = (const float*)d_in[9];
    const float* bo   = (const float*)d_in[10];
    float* out = (float*)d_out;

    __nv_bfloat16 *p_x2, *p_wkq2;
    __half *p_xh, *p_wvh, *p_woh, *p_nh;
    float *p_phase, *p_V;
    cudaGetSymbolAddress((void**)&p_x2,   g_x2);
    cudaGetSymbolAddress((void**)&p_wkq2, g_wkq2);
    cudaGetSymbolAddress((void**)&p_xh,   g_xh);
    cudaGetSymbolAddress((void**)&p_wvh,  g_wvh);
    cudaGetSymbolAddress((void**)&p_woh,  g_woh);
    cudaGetSymbolAddress((void**)&p_nh,   g_nh);
    cudaGetSymbolAddress((void**)&p_phase, g_phase);
    cudaGetSymbolAddress((void**)&p_V,     g_V);

    cudaFuncSetAttribute((const void*)gemm_phase,
                         cudaFuncAttributeMaxDynamicSharedMemorySize, (int)PH_SMEM);
    cudaFuncSetAttribute((const void*)gemm_big<0>,
                         cudaFuncAttributeMaxDynamicSharedMemorySize, (int)BIG_SMEM);
    cudaFuncSetAttribute((const void*)gemm_big<1>,
                         cudaFuncAttributeMaxDynamicSharedMemorySize, (int)BIG_SMEM);

    // prep
    size_t nx = (size_t)B_ROWS * DIM / 4;
    prep_x<<<(unsigned)((nx + 255) / 256), 256>>>(x, nx);
    size_t nw = (size_t)DIM * DIM / 4;
    to_half<<<(unsigned)((nw + 255) / 256), 256>>>(Wv, p_wvh, nw);
    to_half<<<(unsigned)((nw + 255) / 256), 256>>>(Wo, p_woh, nw);
    size_t nk = (size_t)64 * DIM / 4;
    split2_w<<<(unsigned)((nk + 255) / 256), 256>>>(Wk, p_wkq2, nk);
    split2_w<<<(unsigned)((nk + 255) / 256), 256>>>(Wq, p_wkq2 + (size_t)64 * K2, nk);

    // V raw = x @ Wv^T
    gemm_big<0><<<(B_ROWS / BM2) * (DIM / BN2), 256, BIG_SMEM>>>(
        p_xh, p_wvh, p_V, B_ROWS, DIM, DIM, nullptr, nullptr);

    // phase scores (3 segment-pair passes)
    gemm_phase<<<dim3(B_ROWS / BM, 3), 256, PH_SMEM>>>(
        p_x2, p_wkq2, p_phase, B_ROWS, NPH, DIM);

    // per-row coef
    coef_kernel<<<B_ROWS / 8, 256>>>(bk, bq);

    // bias + coef scale + LayerNorm -> fp16 normed
    ln_kernel<<<B_ROWS, 256>>>(bv, ln_g, ln_b);

    // out = x + normed @ Wo^T + bo
    gemm_big<1><<<(B_ROWS / BM2) * (DIM / BN2), 256, BIG_SMEM>>>(
        p_nh, p_woh, out, B_ROWS, DIM, DIM, bo, x);
}

// round 10
// speedup vs baseline: 1.0744x; 1.0744x over previous
#include <cuda_runtime.h>
#include <cuda_bf16.h>
#include <cuda_fp16.h>
#include <math.h>
#include <stdint.h>

#define B_ROWS 8192
#define DIM    4096
#define NPH    128
#define K2     (2 * DIM)          // [h|l] split storage
#define LN_EPS 1e-5f
#define PI_F   3.14159265358979323846f

// ---------------- scratch (device globals) ----------------------------------
__device__ __nv_bfloat16 g_x2 [(size_t)B_ROWS * K2];    // x split [h|l]
__device__ __nv_bfloat16 g_wkq2[(size_t)NPH * K2];      // [Wk;Wq] split [h|l]
__device__ __half g_xh [(size_t)B_ROWS * DIM];          // x   fp16
__device__ __half g_wvh[(size_t)DIM * DIM];             // Wv  fp16
__device__ __half g_woh[(size_t)DIM * DIM];             // Wo  fp16
__device__ __half g_vh [(size_t)B_ROWS * DIM];          // (V+bv)*coef fp16
__device__ __half g_nh [(size_t)B_ROWS * DIM];          // normed fp16
__device__ float g_phase[3 * (size_t)B_ROWS * NPH];     // 3 split partials
__device__ float g_coef[B_ROWS];

// ---------------- PTX helpers ------------------------------------------------
__device__ __forceinline__ void cp_async16s(uint32_t s, const void* gmem) {
    asm volatile("cp.async.cg.shared.global [%0], [%1], 16;\n" :: "r"(s), "l"(gmem));
}
__device__ __forceinline__ void cp_commit() { asm volatile("cp.async.commit_group;\n"); }
template <int N> __device__ __forceinline__ void cp_wait() {
    asm volatile("cp.async.wait_group %0;\n" :: "n"(N));
}
__device__ __forceinline__ void ldmx4(uint32_t& r0, uint32_t& r1, uint32_t& r2, uint32_t& r3,
                                      uint32_t addr) {
    asm volatile("ldmatrix.sync.aligned.m8n8.x4.shared.b16 {%0,%1,%2,%3}, [%4];"
                 : "=r"(r0), "=r"(r1), "=r"(r2), "=r"(r3) : "r"(addr));
}
__device__ __forceinline__ void mma_f16(float* c, uint32_t a0, uint32_t a1,
                                        uint32_t a2, uint32_t a3,
                                        uint32_t b0, uint32_t b1) {
    asm volatile("mma.sync.aligned.m16n8k16.row.col.f32.f16.f16.f32 "
                 "{%0,%1,%2,%3}, {%4,%5,%6,%7}, {%8,%9}, {%0,%1,%2,%3};"
                 : "+f"(c[0]), "+f"(c[1]), "+f"(c[2]), "+f"(c[3])
                 : "r"(a0), "r"(a1), "r"(a2), "r"(a3), "r"(b0), "r"(b1));
}
__device__ __forceinline__ void mma_bf16(float* c, uint32_t a0, uint32_t a1,
                                         uint32_t a2, uint32_t a3,
                                         uint32_t b0, uint32_t b1) {
    asm volatile("mma.sync.aligned.m16n8k16.row.col.f32.bf16.bf16.f32 "
                 "{%0,%1,%2,%3}, {%4,%5,%6,%7}, {%8,%9}, {%0,%1,%2,%3};"
                 : "+f"(c[0]), "+f"(c[1]), "+f"(c[2]), "+f"(c[3])
                 : "r"(a0), "r"(a1), "r"(a2), "r"(a3), "r"(b0), "r"(b1));
}
__device__ __forceinline__ uint32_t smem_u32(const void* p) {
    uint32_t a;
    asm("{ .reg .u64 t; cvta.to.shared.u64 t, %1; cvt.u32.u64 %0, t; }" : "=r"(a) : "l"(p));
    return a;
}

// --------- x prep: one read -> bf16 [h|l] split AND fp16 ---------------------
__global__ void prep_x(const float* __restrict__ in, size_t n_vec4) {
    size_t i = (size_t)blockIdx.x * blockDim.x + threadIdx.x;
    if (i >= n_vec4) return;
    size_t e = i * 4;
    size_t r = e / DIM;
    int    k = (int)(e % DIM);
    float4 v = *reinterpret_cast<const float4*>(in + e);
    float vv[4] = {v.x, v.y, v.z, v.w};
    union { __nv_bfloat16 b[4]; uint2 u; } H, L;
#pragma unroll
    for (int q = 0; q < 4; q++) {
        H.b[q] = __float2bfloat16_rn(vv[q]);
        L.b[q] = __float2bfloat16_rn(vv[q] - __bfloat162float(H.b[q]));
    }
    __nv_bfloat16* o = g_x2 + r * (size_t)K2 + k;
    *reinterpret_cast<uint2*>(o)       = H.u;
    *reinterpret_cast<uint2*>(o + DIM) = L.u;
    __half2 h0 = __floats2half2_rn(v.x, v.y);
    __half2 h1 = __floats2half2_rn(v.z, v.w);
    uint2 u = {*reinterpret_cast<uint32_t*>(&h0), *reinterpret_cast<uint32_t*>(&h1)};
    *reinterpret_cast<uint2*>(g_xh + e) = u;
}

// ---------------- weight split [h|l] (phase path) ----------------------------
__global__ void split2_w(const float* __restrict__ in, __nv_bfloat16* __restrict__ out,
                         size_t n_vec4) {
    size_t i = (size_t)blockIdx.x * blockDim.x + threadIdx.x;
    if (i >= n_vec4) return;
    size_t e = i * 4;
    size_t r = e / DIM;
    int    k = (int)(e % DIM);
    float4 v = *reinterpret_cast<const float4*>(in + e);
    float vv[4] = {v.x, v.y, v.z, v.w};
    union { __nv_bfloat16 b[4]; uint2 u; } H, L;
#pragma unroll
    for (int q = 0; q < 4; q++) {
        H.b[q] = __float2bfloat16_rn(vv[q]);
        L.b[q] = __float2bfloat16_rn(vv[q] - __bfloat162float(H.b[q]));
    }
    __nv_bfloat16* o = out + r * (size_t)K2 + k;
    *reinterpret_cast<uint2*>(o)       = H.u;
    *reinterpret_cast<uint2*>(o + DIM) = L.u;
}

// ---------------- fp32 -> fp16 convert ---------------------------------------
__global__ void to_half(const float* __restrict__ in, __half* __restrict__ out, size_t n_vec4) {
    size_t i = (size_t)blockIdx.x * blockDim.x + threadIdx.x;
    if (i >= n_vec4) return;
    float4 v = *reinterpret_cast<const float4*>(in + i * 4);
    __half2 h0 = __floats2half2_rn(v.x, v.y);
    __half2 h1 = __floats2half2_rn(v.z, v.w);
    uint2 u = {*reinterpret_cast<uint32_t*>(&h0), *reinterpret_cast<uint32_t*>(&h1)};
    *reinterpret_cast<uint2*>(out + i * 4) = u;
}

// ---------------- per-row phase alignment -> coef (sums 3 partials) ----------
__global__ void coef_kernel(const float* __restrict__ bk, const float* __restrict__ bq) {
    int row  = blockIdx.x * 8 + (threadIdx.x >> 5);
    int lane = threadIdx.x & 31;
    const size_t SEG = (size_t)B_ROWS * NPH;
    const float* ph = &g_phase[(size_t)row * NPH];
    float s = 0.f;
#pragma unroll
    for (int p = lane; p < 64; p += 32) {
        float rk = ph[p]      + ph[SEG + p]      + ph[2*SEG + p];
        float rq = ph[64 + p] + ph[SEG + 64 + p] + ph[2*SEG + 64 + p];
        float kp = tanhf(rk + bk[p]) * PI_F;
        float qp = tanhf(rq + bq[p]) * PI_F;
        s += cosf(kp - qp);
    }
#pragma unroll
    for (int o = 16; o; o >>= 1) s += __shfl_xor_sync(0xffffffffu, s, o);
    if (lane == 0) {
        float gain = log1pf(expf(s * (1.0f / 64.0f) + 0.5f));
        g_coef[row] = s * gain * (1.0f / 64.0f);
    }
}

// ------- LayerNorm v2: fp16 in ((V+bv)*coef), fp16 out -----------------------
__global__ __launch_bounds__(256) void ln_kernel(const float* __restrict__ ln_g,
                                                 const float* __restrict__ ln_b) {
    int row = blockIdx.x;
    const __half* vr = g_vh + (size_t)row * DIM;
    __half* nr = g_nh + (size_t)row * DIM;
    int tid = threadIdx.x;

    float vals[16];
    float sum = 0.f, sq = 0.f;
#pragma unroll
    for (int j = 0; j < 4; j++) {
        int k = (tid + j * 256) * 4;
        uint2 u = *reinterpret_cast<const uint2*>(vr + k);
        __half2 h0 = *reinterpret_cast<__half2*>(&u.x);
        __half2 h1 = *reinterpret_cast<__half2*>(&u.y);
        float2 f0 = __half22float2(h0);
        float2 f1 = __half22float2(h1);
        vals[j*4+0]=f0.x; vals[j*4+1]=f0.y; vals[j*4+2]=f1.x; vals[j*4+3]=f1.y;
        sum += f0.x+f0.y+f1.x+f1.y;
        sq  += f0.x*f0.x+f0.y*f0.y+f1.x*f1.x+f1.y*f1.y;
    }
    __shared__ float s1[8], s2[8];
#pragma unroll
    for (int o = 16; o; o >>= 1) {
        sum += __shfl_xor_sync(0xffffffffu, sum, o);
        sq  += __shfl_xor_sync(0xffffffffu, sq,  o);
    }
    int warp = tid >> 5, lane = tid & 31;
    if (lane == 0) { s1[warp] = sum; s2[warp] = sq; }
    __syncthreads();
    sum = 0.f; sq = 0.f;
#pragma unroll
    for (int w = 0; w < 8; w++) { sum += s1[w]; sq += s2[w]; }

    float mu   = sum * (1.0f / DIM);
    float var  = sq * (1.0f / DIM) - mu * mu;
    float rstd = rsqrtf(var + LN_EPS);
#pragma unroll
    for (int j = 0; j < 4; j++) {
        int k = (tid + j * 256) * 4;
        float4 g = *reinterpret_cast<const float4*>(ln_g + k);
        float4 bb = *reinterpret_cast<const float4*>(ln_b + k);
        __half2 h0 = __floats2half2_rn((vals[j*4+0]-mu)*rstd*g.x + bb.x,
                                       (vals[j*4+1]-mu)*rstd*g.y + bb.y);
        __half2 h1 = __floats2half2_rn((vals[j*4+2]-mu)*rstd*g.z + bb.z,
                                       (vals[j*4+3]-mu)*rstd*g.w + bb.w);
        uint2 u = {*reinterpret_cast<uint32_t*>(&h0), *reinterpret_cast<uint32_t*>(&h1)};
        *reinterpret_cast<uint2*>(nr + k) = u;
    }
}

// ================= shared GEMM geometry (R8 winner) ===========================
constexpr int BM = 128, BN = 128, BK = 64;
constexpr int STAGES = 3;
constexpr int TILE_B = 128 * 128;                         // bytes per operand stage
constexpr size_t GEMM_SMEM = (size_t)STAGES * 2 * TILE_B; // 98304

// ======== phase GEMM: raw mma.sync bf16, 3 segment-pair passes ================
// seg 0: Ah*Bh   seg 1: Ah*Bl   seg 2: Al*Bh ; C partials [3][M,128]
__global__ __launch_bounds__(256, 2) void gemm_phase(
    const __nv_bfloat16* __restrict__ A, const __nv_bfloat16* __restrict__ Bw,
    float* __restrict__ C, int M, int K)
{
    extern __shared__ __align__(128) unsigned char dsmem[];
    uint32_t sb = smem_u32(dsmem);
    uint32_t sA = sb;
    uint32_t sB = sb + STAGES * TILE_B;

    int seg = blockIdx.y;
    A  += (seg == 2) ? DIM : 0;
    Bw += (seg == 1) ? DIM : 0;
    C  += (size_t)seg * (size_t)M * NPH;

    int tid  = threadIdx.x;
    int warp = tid >> 5;
    int lane = tid & 31;

    int m0 = blockIdx.x * BM;
    int wm = (warp & 3) * 32;
    int wn = (warp >> 2) * 64;

    int chunk = tid & 7;
    int row0  = tid >> 3;
    const __nv_bfloat16* gA = A  + (size_t)m0 * K2 + chunk * 8;
    const __nv_bfloat16* gB = Bw + chunk * 8;

    auto load_tile = [&](int kt, int stg) {
        size_t koff = (size_t)kt * BK;
        uint32_t dA = sA + stg * TILE_B;
        uint32_t dB = sB + stg * TILE_B;
#pragma unroll
        for (int p = 0; p < 4; p++) {
            int r = row0 + p * 32;
            uint32_t so = r * 128 + ((chunk * 16) ^ ((r & 7) << 4));
            cp_async16s(dA + so, gA + (size_t)r * K2 + koff);
            cp_async16s(dB + so, gB + (size_t)r * K2 + koff);
        }
    };

    int lr = lane & 15;
    int kb = lane >> 4;
    uint32_t xv = (uint32_t)((lr & 7) << 4);
    uint32_t aRow0 = (uint32_t)(wm + lr) * 128;
    uint32_t bRow0 = (uint32_t)(wn + lr) * 128;

    float acc[2][8][4];
#pragma unroll
    for (int i = 0; i < 2; i++)
#pragma unroll
        for (int j = 0; j < 8; j++)
#pragma unroll
            for (int q = 0; q < 4; q++) acc[i][j][q] = 0.f;

    const int nt = K / BK;
#pragma unroll
    for (int s = 0; s < STAGES - 1; s++) { load_tile(s, s); cp_commit(); }

    for (int it = 0; it < nt; it++) {
        cp_wait<STAGES - 2>();
        __syncthreads();
        int pre = it + STAGES - 1;
        if (pre < nt) { load_tile(pre, pre % STAGES); cp_commit(); }

        uint32_t tA = sA + (it % STAGES) * TILE_B;
        uint32_t tB = sB + (it % STAGES) * TILE_B;
#pragma unroll
        for (int s16 = 0; s16 < 4; s16++) {
            uint32_t col = (uint32_t)((s16 * 32 + kb * 16)) ^ xv;
            uint32_t a[2][4];
#pragma unroll
            for (int mi = 0; mi < 2; mi++)
                ldmx4(a[mi][0], a[mi][1], a[mi][2], a[mi][3],
                      tA + aRow0 + (uint32_t)(mi * 16 * 128) + col);
            uint32_t b[4][4];
#pragma unroll
            for (int nb = 0; nb < 4; nb++)
                ldmx4(b[nb][0], b[nb][1], b[nb][2], b[nb][3],
                      tB + bRow0 + (uint32_t)(nb * 16 * 128) + col);
#pragma unroll
            for (int mi = 0; mi < 2; mi++)
#pragma unroll
                for (int nb = 0; nb < 4; nb++) {
                    mma_bf16(acc[mi][nb * 2 + 0], a[mi][0], a[mi][1], a[mi][2], a[mi][3],
                             b[nb][0], b[nb][2]);
                    mma_bf16(acc[mi][nb * 2 + 1], a[mi][0], a[mi][1], a[mi][2], a[mi][3],
                             b[nb][1], b[nb][3]);
                }
        }
    }
    cp_wait<0>();

    int mrow = m0 + wm + (lane >> 2);
    int ncol = wn + (lane & 3) * 2;
#pragma unroll
    for (int mi = 0; mi < 2; mi++) {
#pragma unroll
        for (int nj = 0; nj < 8; nj++) {
            int n = ncol + nj * 8;
            size_t go0 = (size_t)(mrow + mi * 16)     * NPH + n;
            size_t go1 = (size_t)(mrow + mi * 16 + 8) * NPH + n;
            *reinterpret_cast<float2*>(C + go0) = {acc[mi][nj][0], acc[mi][nj][1]};
            *reinterpret_cast<float2*>(C + go1) = {acc[mi][nj][2], acc[mi][nj][3]};
        }
    }
}

// ======== big GEMM: raw mma.sync fp16, 128x128, 2 CTA/SM (R8) =================
// MODE 1: Cf[go] = acc + bias[n] + addend[go]          (final output)
// MODE 2: Ch[go] = (__half)((acc + bias[n]) * coef[m]) (V path)
template <int MODE>
__global__ __launch_bounds__(256, 2) void gemm_big(
    const __half* __restrict__ A, const __half* __restrict__ Bw,
    float* __restrict__ Cf, __half* __restrict__ Ch, int M, int N, int K,
    const float* __restrict__ bias, const float* __restrict__ addend,
    const float* __restrict__ coef)
{
    extern __shared__ __align__(128) unsigned char dsmem[];
    uint32_t sb = smem_u32(dsmem);
    uint32_t sA = sb;
    uint32_t sB = sb + STAGES * TILE_B;

    int tid  = threadIdx.x;
    int warp = tid >> 5;
    int lane = tid & 31;

    const int num_m = M / BM, num_n = N / BN;
    const int GROUP = 8;
    int id = blockIdx.x;
    int group_size = GROUP * num_n;
    int gid = id / group_size;
    int first_m = gid * GROUP;
    int gm_sz = (num_m - first_m) < GROUP ? (num_m - first_m) : GROUP;
    int pid_m = first_m + (id % group_size) % gm_sz;
    int pid_n = (id % group_size) / gm_sz;
    int m0 = pid_m * BM;
    int n0 = pid_n * BN;

    int wm = (warp & 3) * 32;
    int wn = (warp >> 2) * 64;

    int chunk = tid & 7;
    int row0  = tid >> 3;
    const __half* gA = A  + (size_t)m0 * K + chunk * 8;
    const __half* gB = Bw + (size_t)n0 * K + chunk * 8;

    auto load_tile = [&](int kt, int stg) {
        size_t koff = (size_t)kt * BK;
        uint32_t dA = sA + stg * TILE_B;
        uint32_t dB = sB + stg * TILE_B;
#pragma unroll
        for (int p = 0; p < 4; p++) {
            int r = row0 + p * 32;
            uint32_t so = r * 128 + ((chunk * 16) ^ ((r & 7) << 4));
            cp_async16s(dA + so, gA + (size_t)r * K + koff);
            cp_async16s(dB + so, gB + (size_t)r * K + koff);
        }
    };

    int lr = lane & 15;
    int kb = lane >> 4;
    uint32_t xv = (uint32_t)((lr & 7) << 4);
    uint32_t aRow0 = (uint32_t)(wm + lr) * 128;
    uint32_t bRow0 = (uint32_t)(wn + lr) * 128;

    float acc[2][8][4];
#pragma unroll
    for (int i = 0; i < 2; i++)
#pragma unroll
        for (int j = 0; j < 8; j++)
#pragma unroll
            for (int q = 0; q < 4; q++) acc[i][j][q] = 0.f;

    const int nt = K / BK;
#pragma unroll
    for (int s = 0; s < STAGES - 1; s++) { load_tile(s, s); cp_commit(); }

    for (int it = 0; it < nt; it++) {
        cp_wait<STAGES - 2>();
        __syncthreads();
        int pre = it + STAGES - 1;
        if (pre < nt) { load_tile(pre, pre % STAGES); cp_commit(); }

        uint32_t tA = sA + (it % STAGES) * TILE_B;
        uint32_t tB = sB + (it % STAGES) * TILE_B;
#pragma unroll
        for (int s16 = 0; s16 < 4; s16++) {
            uint32_t col = (uint32_t)((s16 * 32 + kb * 16)) ^ xv;
            uint32_t a[2][4];
#pragma unroll
            for (int mi = 0; mi < 2; mi++)
                ldmx4(a[mi][0], a[mi][1], a[mi][2], a[mi][3],
                      tA + aRow0 + (uint32_t)(mi * 16 * 128) + col);
            uint32_t b[4][4];
#pragma unroll
            for (int nb = 0; nb < 4; nb++)
                ldmx4(b[nb][0], b[nb][1], b[nb][2], b[nb][3],
                      tB + bRow0 + (uint32_t)(nb * 16 * 128) + col);
#pragma unroll
            for (int mi = 0; mi < 2; mi++)
#pragma unroll
                for (int nb = 0; nb < 4; nb++) {
                    mma_f16(acc[mi][nb * 2 + 0], a[mi][0], a[mi][1], a[mi][2], a[mi][3],
                            b[nb][0], b[nb][2]);
                    mma_f16(acc[mi][nb * 2 + 1], a[mi][0], a[mi][1], a[mi][2], a[mi][3],
                            b[nb][1], b[nb][3]);
                }
        }
    }
    cp_wait<0>();

    int mrow = m0 + wm + (lane >> 2);
    int ncol = n0 + wn + (lane & 3) * 2;
#pragma unroll
    for (int mi = 0; mi < 2; mi++) {
        float cf0 = 0.f, cf1 = 0.f;
        if (MODE == 2) {
            cf0 = coef[mrow + mi * 16];
            cf1 = coef[mrow + mi * 16 + 8];
        }
#pragma unroll
        for (int nj = 0; nj < 8; nj++) {
            int n = ncol + nj * 8;
            size_t go0 = (size_t)(mrow + mi * 16)     * N + n;
            size_t go1 = (size_t)(mrow + mi * 16 + 8) * N + n;
            float2 bb = *reinterpret_cast<const float2*>(bias + n);
            if (MODE == 1) {
                float2 a0 = *reinterpret_cast<const float2*>(addend + go0);
                float2 a1 = *reinterpret_cast<const float2*>(addend + go1);
                float2 v0 = {acc[mi][nj][0] + bb.x + a0.x, acc[mi][nj][1] + bb.y + a0.y};
                float2 v1 = {acc[mi][nj][2] + bb.x + a1.x, acc[mi][nj][3] + bb.y + a1.y};
                *reinterpret_cast<float2*>(Cf + go0) = v0;
                *reinterpret_cast<float2*>(Cf + go1) = v1;
            } else {
                __half2 h0 = __floats2half2_rn((acc[mi][nj][0] + bb.x) * cf0,
                                               (acc[mi][nj][1] + bb.y) * cf0);
                __half2 h1 = __floats2half2_rn((acc[mi][nj][2] + bb.x) * cf1,
                                               (acc[mi][nj][3] + bb.y) * cf1);
                *reinterpret_cast<__half2*>(Ch + go0) = h0;
                *reinterpret_cast<__half2*>(Ch + go1) = h1;
            }
        }
    }
}

// ---------------- launch -----------------------------------------------------
extern "C" void kernel_launch(void* const* d_in, const int* in_sizes, int n_in,
                              void* d_out, int out_size) {
    const float* x    = (const float*)d_in[0];
    const float* Wk   = (const float*)d_in[1];
    const float* bk   = (const float*)d_in[2];
    const float* Wq   = (const float*)d_in[3];
    const float* bq   = (const float*)d_in[4];
    const float* Wv   = (const float*)d_in[5];
    const float* bv   = (const float*)d_in[6];
    const float* ln_g = (const float*)d_in[7];
    const float* ln_b = (const float*)d_in[8];
    const float* Wo   = (const float*)d_in[9];
    const float* bo   = (const float*)d_in[10];
    float* out = (float*)d_out;

    __nv_bfloat16 *p_x2, *p_wkq2;
    __half *p_xh, *p_wvh, *p_woh, *p_vh, *p_nh;
    float *p_phase, *p_coef;
    cudaGetSymbolAddress((void**)&p_x2,   g_x2);
    cudaGetSymbolAddress((void**)&p_wkq2, g_wkq2);
    cudaGetSymbolAddress((void**)&p_xh,   g_xh);
    cudaGetSymbolAddress((void**)&p_wvh,  g_wvh);
    cudaGetSymbolAddress((void**)&p_woh,  g_woh);
    cudaGetSymbolAddress((void**)&p_vh,   g_vh);
    cudaGetSymbolAddress((void**)&p_nh,   g_nh);
    cudaGetSymbolAddress((void**)&p_phase, g_phase);
    cudaGetSymbolAddress((void**)&p_coef,  g_coef);

    cudaFuncSetAttribute((const void*)gemm_phase,
                         cudaFuncAttributeMaxDynamicSharedMemorySize, (int)GEMM_SMEM);
    cudaFuncSetAttribute((const void*)gemm_big<1>,
                         cudaFuncAttributeMaxDynamicSharedMemorySize, (int)GEMM_SMEM);
    cudaFuncSetAttribute((const void*)gemm_big<2>,
                         cudaFuncAttributeMaxDynamicSharedMemorySize, (int)GEMM_SMEM);

    // prep
    size_t nx = (size_t)B_ROWS * DIM / 4;
    prep_x<<<(unsigned)((nx + 255) / 256), 256>>>(x, nx);
    size_t nw = (size_t)DIM * DIM / 4;
    to_half<<<(unsigned)((nw + 255) / 256), 256>>>(Wv, p_wvh, nw);
    to_half<<<(unsigned)((nw + 255) / 256), 256>>>(Wo, p_woh, nw);
    size_t nk = (size_t)64 * DIM / 4;
    split2_w<<<(unsigned)((nk + 255) / 256), 256>>>(Wk, p_wkq2, nk);
    split2_w<<<(unsigned)((nk + 255) / 256), 256>>>(Wq, p_wkq2 + (size_t)64 * K2, nk);

    // phase scores (3 segment-pair passes) -> coef
    gemm_phase<<<dim3(B_ROWS / BM, 3), 256, GEMM_SMEM>>>(
        p_x2, p_wkq2, p_phase, B_ROWS, DIM);
    coef_kernel<<<B_ROWS / 8, 256>>>(bk, bq);

    // V path: g_vh = (x @ Wv^T + bv) * coef   (fp16)
    gemm_big<2><<<(B_ROWS / BM) * (DIM / BN), 256, GEMM_SMEM>>>(
        p_xh, p_wvh, nullptr, p_vh, B_ROWS, DIM, DIM, bv, nullptr, p_coef);

    // LayerNorm -> fp16 normed
    ln_kernel<<<B_ROWS, 256>>>(ln_g, ln_b);

    // out = x + normed @ Wo^T + bo
    gemm_big<1><<<(B_ROWS / BM) * (DIM / BN), 256, GEMM_SMEM>>>(
        p_nh, p_woh, out, nullptr, B_ROWS, DIM, DIM, bo, x, nullptr);
}